// round 4
// baseline (speedup 1.0000x reference)
#include <cuda_runtime.h>
#include <cuda_fp16.h>
#include <cstdint>

#define N_USER 50000
#define N_ITEM 100000
#define NTOT   150000
#define NNZ    3000000
#define EMB    64
#define BATCH  4096
#define NBLK_SCAN 147   // ceil(150000/1024)

// ---------------- device scratch (no allocation allowed) --------------------
__device__ __align__(16) __half2 g_egoA[(size_t)NTOT * 32];   // fp16 ego ping
__device__ __align__(16) __half2 g_egoB[(size_t)NTOT * 32];   // fp16 ego pong
__device__ __align__(16) float   g_total[(size_t)NTOT * EMB]; // fp32 accumulator
__device__ __align__(16) unsigned long long g_edges[NNZ];     // {col lo32, val hi32}
__device__ int g_cnt[NTOT];
__device__ int g_start[NTOT];
__device__ int g_cur[NTOT];
__device__ int g_bsum[NBLK_SCAN];

// ---------------------------------------------------------------------------
// init: total = concat(user_emb, item_emb) (fp32); egoA = fp16(same); cnt = 0
// ---------------------------------------------------------------------------
__global__ void k_init(const float4* __restrict__ ue, const float4* __restrict__ ie) {
    int i = blockIdx.x * blockDim.x + threadIdx.x;   // NTOT*16 float4s
    if (i < NTOT) g_cnt[i] = 0;
    if (i >= NTOT * 16) return;
    float4 v = (i < N_USER * 16) ? ue[i] : ie[i - N_USER * 16];
    reinterpret_cast<float4*>(g_total)[i] = v;
    g_egoA[2 * i]     = __floats2half2_rn(v.x, v.y);
    g_egoA[2 * i + 1] = __floats2half2_rn(v.z, v.w);
}

// ---------------------------------------------------------------------------
// CSR build
// ---------------------------------------------------------------------------
__global__ void k_hist(const int* __restrict__ rows) {
    int i = blockIdx.x * blockDim.x + threadIdx.x;
    if (i < NNZ) atomicAdd(&g_cnt[rows[i]], 1);
}

__global__ void k_scanA() {
    __shared__ int s[1024];
    int t = threadIdx.x;
    int g = blockIdx.x * 1024 + t;
    int v = (g < NTOT) ? g_cnt[g] : 0;
    s[t] = v;
    __syncthreads();
#pragma unroll
    for (int off = 1; off < 1024; off <<= 1) {
        int add = (t >= off) ? s[t - off] : 0;
        __syncthreads();
        s[t] += add;
        __syncthreads();
    }
    if (g < NTOT) g_start[g] = s[t] - v;
    if (t == 1023) g_bsum[blockIdx.x] = s[1023];
}

__global__ void k_scanB() {
    __shared__ int s[256];
    int t = threadIdx.x;
    int v = (t < NBLK_SCAN) ? g_bsum[t] : 0;
    s[t] = v;
    __syncthreads();
#pragma unroll
    for (int off = 1; off < 256; off <<= 1) {
        int add = (t >= off) ? s[t - off] : 0;
        __syncthreads();
        s[t] += add;
        __syncthreads();
    }
    if (t < NBLK_SCAN) g_bsum[t] = s[t] - v;
}

__global__ void k_scanC() {
    int g = blockIdx.x * 1024 + threadIdx.x;
    if (g >= NTOT) return;
    int off = g_start[g] + g_bsum[blockIdx.x];
    g_start[g] = off;
    g_cur[g]   = off;
}

__global__ void k_fill(const int* __restrict__ rows, const int* __restrict__ cols,
                       const float* __restrict__ vals) {
    int i = blockIdx.x * blockDim.x + threadIdx.x;
    if (i >= NNZ) return;
    int r = rows[i];
    int p = atomicAdd(&g_cur[r], 1);
    g_edges[p] = (unsigned long long)(unsigned)cols[i]
               | ((unsigned long long)__float_as_uint(vals[i]) << 32);
}

// ---------------------------------------------------------------------------
// fused layer.  Warp = 4 rows; lane owns cols {2l, 2l+1}.
// Phase 1 interleaves the 4 rows' edge streams round-robin: each while-loop
// iteration issues a 4-edge chunk for EACH still-active row, so up to 16
// gathers + 16 edge loads are outstanding concurrently (vs 4/row serial
// before). Loop guards are warp-uniform (no divergence).
// ---------------------------------------------------------------------------
__global__ void __launch_bounds__(256)
k_layer(const __half2* __restrict__ ego_in, __half2* __restrict__ ego_out,
        const float* __restrict__ W, const float* __restrict__ b) {
    __shared__ float Ws[EMB * EMB];
    __shared__ float srow[8][EMB][4];   // [warp][k][row-in-group]

    int tid = threadIdx.x;
    for (int i = tid; i < EMB * EMB / 4; i += 256)
        reinterpret_cast<float4*>(Ws)[i] = reinterpret_cast<const float4*>(W)[i];
    __syncthreads();

    int warp = tid >> 5, lane = tid & 31;
    int r0 = (blockIdx.x * 8 + warp) * 4;
    if (r0 >= NTOT) return;

    // ---- phase 1: interleaved segmented gather for 4 rows ----
    int   n[4], j[4];
    const unsigned long long* ep[4];
    float2 acc[4];
#pragma unroll
    for (int r = 0; r < 4; r++) {
        int row = r0 + r;
        bool ok = row < NTOT;
        n[r]   = ok ? g_cnt[row] : 0;
        ep[r]  = &g_edges[ok ? g_start[row] : 0];
        j[r]   = 0;
        acc[r] = make_float2(0.f, 0.f);
    }

    bool any = (j[0] + 4 <= n[0]) | (j[1] + 4 <= n[1]) |
               (j[2] + 4 <= n[2]) | (j[3] + 4 <= n[3]);
    while (any) {
#pragma unroll
        for (int r = 0; r < 4; r++) {
            if (j[r] + 4 <= n[r]) {                 // warp-uniform
                const unsigned long long* p = ep[r] + j[r];
                unsigned long long e0 = __ldcs(p);
                unsigned long long e1 = __ldcs(p + 1);
                unsigned long long e2 = __ldcs(p + 2);
                unsigned long long e3 = __ldcs(p + 3);
                __half2 x0 = ego_in[(size_t)(unsigned)e0 * 32 + lane];
                __half2 x1 = ego_in[(size_t)(unsigned)e1 * 32 + lane];
                __half2 x2 = ego_in[(size_t)(unsigned)e2 * 32 + lane];
                __half2 x3 = ego_in[(size_t)(unsigned)e3 * 32 + lane];
                float v0 = __uint_as_float((unsigned)(e0 >> 32));
                float v1 = __uint_as_float((unsigned)(e1 >> 32));
                float v2 = __uint_as_float((unsigned)(e2 >> 32));
                float v3 = __uint_as_float((unsigned)(e3 >> 32));
                float2 f0 = __half22float2(x0);
                float2 f1 = __half22float2(x1);
                float2 f2 = __half22float2(x2);
                float2 f3 = __half22float2(x3);
                acc[r].x += v0 * f0.x; acc[r].y += v0 * f0.y;
                acc[r].x += v1 * f1.x; acc[r].y += v1 * f1.y;
                acc[r].x += v2 * f2.x; acc[r].y += v2 * f2.y;
                acc[r].x += v3 * f3.x; acc[r].y += v3 * f3.y;
                j[r] += 4;
            }
        }
        any = (j[0] + 4 <= n[0]) | (j[1] + 4 <= n[1]) |
              (j[2] + 4 <= n[2]) | (j[3] + 4 <= n[3]);
    }
    // tails (0-3 edges per row)
#pragma unroll
    for (int r = 0; r < 4; r++) {
        for (; j[r] < n[r]; j[r]++) {
            unsigned long long e = __ldcs(ep[r] + j[r]);
            __half2 x = ego_in[(size_t)(unsigned)e * 32 + lane];
            float  v = __uint_as_float((unsigned)(e >> 32));
            float2 f = __half22float2(x);
            acc[r].x += v * f.x; acc[r].y += v * f.y;
        }
        srow[warp][2 * lane][r]     = acc[r].x;
        srow[warp][2 * lane + 1][r] = acc[r].y;
    }
    __syncwarp();

    // ---- phase 2: batched 4-row matmul (W in smem) ----
    const float2 bias = *reinterpret_cast<const float2*>(&b[2 * lane]);
    float2 o0 = bias, o1 = bias, o2 = bias, o3 = bias;
#pragma unroll
    for (int k = 0; k < EMB; k++) {
        float4 s4 = *reinterpret_cast<const float4*>(&srow[warp][k][0]);  // bcast
        float2 wk = *reinterpret_cast<const float2*>(&Ws[k * EMB + 2 * lane]);
        o0.x += s4.x * wk.x; o0.y += s4.x * wk.y;
        o1.x += s4.y * wk.x; o1.y += s4.y * wk.y;
        o2.x += s4.z * wk.x; o2.y += s4.z * wk.y;
        o3.x += s4.w * wk.x; o3.y += s4.w * wk.y;
    }

    // ---- phase 3: leaky_relu, write fp16 ego_out (skipped on last layer),
    //      l2norm accumulate into total ----
    float2 os[4] = {o0, o1, o2, o3};
#pragma unroll
    for (int r = 0; r < 4; r++) {
        int row = r0 + r;
        if (row >= NTOT) break;
        float2 e;
        e.x = os[r].x > 0.f ? os[r].x : 0.2f * os[r].x;
        e.y = os[r].y > 0.f ? os[r].y : 0.2f * os[r].y;

        if (ego_out) ego_out[(size_t)row * 32 + lane] = __floats2half2_rn(e.x, e.y);

        float ss = e.x * e.x + e.y * e.y;
#pragma unroll
        for (int off = 16; off; off >>= 1)
            ss += __shfl_xor_sync(0xffffffffu, ss, off);
        float inv = 1.f / fmaxf(sqrtf(ss), 1e-12f);

        float2* tp = reinterpret_cast<float2*>(&g_total[(size_t)row * EMB + 2 * lane]);
        float2 t = *tp;
        t.x += e.x * inv;
        t.y += e.y * inv;
        *tp = t;
    }
}

// ---------------------------------------------------------------------------
__global__ void k_out(const int* __restrict__ users, float4* __restrict__ out) {
    int i = blockIdx.x * blockDim.x + threadIdx.x;  // BATCH*16 float4s
    if (i >= BATCH * 16) return;
    int bidx = i >> 4, q = i & 15;
    int u = users[bidx];
    out[i] = reinterpret_cast<const float4*>(g_total)[(size_t)u * 16 + q];
}

// ---------------------------------------------------------------------------
extern "C" void kernel_launch(void* const* d_in, const int* in_sizes, int n_in,
                              void* d_out, int out_size) {
    const int*   users = (const int*)d_in[0];
    const int*   rows  = (const int*)d_in[1];
    const int*   cols  = (const int*)d_in[2];
    const float* vals  = (const float*)d_in[3];
    const float* ue    = (const float*)d_in[4];
    const float* ie    = (const float*)d_in[5];
    const float* Wl[3] = {(const float*)d_in[6], (const float*)d_in[8],  (const float*)d_in[10]};
    const float* Bl[3] = {(const float*)d_in[7], (const float*)d_in[9],  (const float*)d_in[11]};

    __half2 *egoA, *egoB;
    cudaGetSymbolAddress((void**)&egoA, g_egoA);
    cudaGetSymbolAddress((void**)&egoB, g_egoB);

    k_init<<<(NTOT * 16 + 255) / 256, 256>>>((const float4*)ue, (const float4*)ie);

    // CSR build
    k_hist<<<(NNZ + 255) / 256, 256>>>(rows);
    k_scanA<<<NBLK_SCAN, 1024>>>();
    k_scanB<<<1, 256>>>();
    k_scanC<<<NBLK_SCAN, 1024>>>();
    k_fill<<<(NNZ + 255) / 256, 256>>>(rows, cols, vals);

    // 3 fused layers, ping-pong fp16 ego buffers; last layer writes no ego
    __half2* ins[3]  = {egoA, egoB, egoA};
    __half2* outs[3] = {egoB, egoA, nullptr};
    for (int l = 0; l < 3; l++)
        k_layer<<<(NTOT + 31) / 32, 256>>>(ins[l], outs[l], Wl[l], Bl[l]);

    k_out<<<(BATCH * 16 + 255) / 256, 256>>>(users, (float4*)d_out);
}

// round 5
// speedup vs baseline: 1.1418x; 1.1418x over previous
#include <cuda_runtime.h>
#include <cuda_fp16.h>
#include <cstdint>

#define N_USER 50000
#define N_ITEM 100000
#define NTOT   150000
#define NNZ    3000000
#define EMB    64
#define BATCH  4096
#define NBLK_SCAN 147   // ceil(150000/1024)

// ---------------- device scratch (no allocation allowed) --------------------
__device__ __align__(16) __half2 g_egoA[(size_t)NTOT * 32];   // fp16 ego ping
__device__ __align__(16) __half2 g_egoB[(size_t)NTOT * 32];   // fp16 ego pong
__device__ __align__(16) float   g_total[(size_t)NTOT * EMB]; // fp32 accumulator
__device__ __align__(16) unsigned long long g_edges[NNZ + 8]; // {col lo32, val hi32}; +8 pad for clamped reads
__device__ int g_cnt[NTOT];
__device__ int g_start[NTOT];
__device__ int g_cur[NTOT];
__device__ int g_bsum[NBLK_SCAN];

// ---------------------------------------------------------------------------
// init: total = concat(user_emb, item_emb) (fp32); egoA = fp16(same); cnt = 0
// ---------------------------------------------------------------------------
__global__ void k_init(const float4* __restrict__ ue, const float4* __restrict__ ie) {
    int i = blockIdx.x * blockDim.x + threadIdx.x;   // NTOT*16 float4s
    if (i < NTOT) g_cnt[i] = 0;
    if (i >= NTOT * 16) return;
    float4 v = (i < N_USER * 16) ? ue[i] : ie[i - N_USER * 16];
    reinterpret_cast<float4*>(g_total)[i] = v;
    g_egoA[2 * i]     = __floats2half2_rn(v.x, v.y);
    g_egoA[2 * i + 1] = __floats2half2_rn(v.z, v.w);
}

// ---------------------------------------------------------------------------
// CSR build
// ---------------------------------------------------------------------------
__global__ void k_hist(const int* __restrict__ rows) {
    int i = blockIdx.x * blockDim.x + threadIdx.x;
    if (i < NNZ) atomicAdd(&g_cnt[rows[i]], 1);
}

__global__ void k_scanA() {
    __shared__ int s[1024];
    int t = threadIdx.x;
    int g = blockIdx.x * 1024 + t;
    int v = (g < NTOT) ? g_cnt[g] : 0;
    s[t] = v;
    __syncthreads();
#pragma unroll
    for (int off = 1; off < 1024; off <<= 1) {
        int add = (t >= off) ? s[t - off] : 0;
        __syncthreads();
        s[t] += add;
        __syncthreads();
    }
    if (g < NTOT) g_start[g] = s[t] - v;
    if (t == 1023) g_bsum[blockIdx.x] = s[1023];
}

__global__ void k_scanB() {
    __shared__ int s[256];
    int t = threadIdx.x;
    int v = (t < NBLK_SCAN) ? g_bsum[t] : 0;
    s[t] = v;
    __syncthreads();
#pragma unroll
    for (int off = 1; off < 256; off <<= 1) {
        int add = (t >= off) ? s[t - off] : 0;
        __syncthreads();
        s[t] += add;
        __syncthreads();
    }
    if (t < NBLK_SCAN) g_bsum[t] = s[t] - v;
}

__global__ void k_scanC() {
    int g = blockIdx.x * 1024 + threadIdx.x;
    if (g >= NTOT) return;
    int off = g_start[g] + g_bsum[blockIdx.x];
    g_start[g] = off;
    g_cur[g]   = off;
}

__global__ void k_fill(const int* __restrict__ rows, const int* __restrict__ cols,
                       const float* __restrict__ vals) {
    int i = blockIdx.x * blockDim.x + threadIdx.x;
    if (i >= NNZ) return;
    int r = rows[i];
    int p = atomicAdd(&g_cur[r], 1);
    g_edges[p] = (unsigned long long)(unsigned)cols[i]
               | ((unsigned long long)__float_as_uint(vals[i]) << 32);
}

// ---------------------------------------------------------------------------
// fused layer.  Warp = 4 rows; lane owns cols {2l, 2l+1}.
// Phase 1: BRANCH-FREE interleave of the 4 rows' edge streams. One loop to
// nmax = max degree of the 4 rows; each iteration unconditionally issues
// 4 edges x 4 rows (clamped index, val zeroed when padded). 16 independent
// edge loads + 16 independent gathers in flight per iteration; no BSSY/BSYNC,
// no serial tails.
// ---------------------------------------------------------------------------
__global__ void __launch_bounds__(256)
k_layer(const __half2* __restrict__ ego_in, __half2* __restrict__ ego_out,
        const float* __restrict__ W, const float* __restrict__ b) {
    __shared__ float Ws[EMB * EMB];
    __shared__ float srow[8][EMB][4];   // [warp][k][row-in-group]

    int tid = threadIdx.x;
    for (int i = tid; i < EMB * EMB / 4; i += 256)
        reinterpret_cast<float4*>(Ws)[i] = reinterpret_cast<const float4*>(W)[i];
    __syncthreads();

    int warp = tid >> 5, lane = tid & 31;
    int r0 = (blockIdx.x * 8 + warp) * 4;
    if (r0 >= NTOT) return;

    // ---- phase 1 ----
    int n[4];
    const unsigned long long* ep[4];
    float2 acc[4];
    int nmax = 0;
#pragma unroll
    for (int r = 0; r < 4; r++) {
        int row = r0 + r;
        bool ok = row < NTOT;
        n[r]   = ok ? g_cnt[row] : 0;
        ep[r]  = &g_edges[ok ? g_start[row] : 0];
        acc[r] = make_float2(0.f, 0.f);
        nmax   = max(nmax, n[r]);
    }

    for (int base = 0; base < nmax; base += 4) {
        unsigned long long e[4][4];
#pragma unroll
        for (int r = 0; r < 4; r++)
#pragma unroll
            for (int t = 0; t < 4; t++) {
                int q = (base + t < n[r]) ? base + t : 0;   // clamp (safe addr)
                e[r][t] = __ldcs(ep[r] + q);
            }
#pragma unroll
        for (int r = 0; r < 4; r++)
#pragma unroll
            for (int t = 0; t < 4; t++) {
                __half2 x = ego_in[(size_t)(unsigned)e[r][t] * 32 + lane];
                float v = (base + t < n[r])
                        ? __uint_as_float((unsigned)(e[r][t] >> 32)) : 0.f;
                float2 f = __half22float2(x);
                acc[r].x += v * f.x;
                acc[r].y += v * f.y;
            }
    }

#pragma unroll
    for (int r = 0; r < 4; r++) {
        srow[warp][2 * lane][r]     = acc[r].x;
        srow[warp][2 * lane + 1][r] = acc[r].y;
    }
    __syncwarp();

    // ---- phase 2: batched 4-row matmul (W in smem) ----
    const float2 bias = *reinterpret_cast<const float2*>(&b[2 * lane]);
    float2 o0 = bias, o1 = bias, o2 = bias, o3 = bias;
#pragma unroll
    for (int k = 0; k < EMB; k++) {
        float4 s4 = *reinterpret_cast<const float4*>(&srow[warp][k][0]);  // bcast
        float2 wk = *reinterpret_cast<const float2*>(&Ws[k * EMB + 2 * lane]);
        o0.x += s4.x * wk.x; o0.y += s4.x * wk.y;
        o1.x += s4.y * wk.x; o1.y += s4.y * wk.y;
        o2.x += s4.z * wk.x; o2.y += s4.z * wk.y;
        o3.x += s4.w * wk.x; o3.y += s4.w * wk.y;
    }

    // ---- phase 3: leaky_relu, write fp16 ego_out (skipped on last layer),
    //      l2norm accumulate into total ----
    float2 os[4] = {o0, o1, o2, o3};
#pragma unroll
    for (int r = 0; r < 4; r++) {
        int row = r0 + r;
        if (row >= NTOT) break;
        float2 e;
        e.x = os[r].x > 0.f ? os[r].x : 0.2f * os[r].x;
        e.y = os[r].y > 0.f ? os[r].y : 0.2f * os[r].y;

        if (ego_out) ego_out[(size_t)row * 32 + lane] = __floats2half2_rn(e.x, e.y);

        float ss = e.x * e.x + e.y * e.y;
#pragma unroll
        for (int off = 16; off; off >>= 1)
            ss += __shfl_xor_sync(0xffffffffu, ss, off);
        float inv = 1.f / fmaxf(sqrtf(ss), 1e-12f);

        float2* tp = reinterpret_cast<float2*>(&g_total[(size_t)row * EMB + 2 * lane]);
        float2 t = *tp;
        t.x += e.x * inv;
        t.y += e.y * inv;
        *tp = t;
    }
}

// ---------------------------------------------------------------------------
__global__ void k_out(const int* __restrict__ users, float4* __restrict__ out) {
    int i = blockIdx.x * blockDim.x + threadIdx.x;  // BATCH*16 float4s
    if (i >= BATCH * 16) return;
    int bidx = i >> 4, q = i & 15;
    int u = users[bidx];
    out[i] = reinterpret_cast<const float4*>(g_total)[(size_t)u * 16 + q];
}

// ---------------------------------------------------------------------------
extern "C" void kernel_launch(void* const* d_in, const int* in_sizes, int n_in,
                              void* d_out, int out_size) {
    const int*   users = (const int*)d_in[0];
    const int*   rows  = (const int*)d_in[1];
    const int*   cols  = (const int*)d_in[2];
    const float* vals  = (const float*)d_in[3];
    const float* ue    = (const float*)d_in[4];
    const float* ie    = (const float*)d_in[5];
    const float* Wl[3] = {(const float*)d_in[6], (const float*)d_in[8],  (const float*)d_in[10]};
    const float* Bl[3] = {(const float*)d_in[7], (const float*)d_in[9],  (const float*)d_in[11]};

    __half2 *egoA, *egoB;
    cudaGetSymbolAddress((void**)&egoA, g_egoA);
    cudaGetSymbolAddress((void**)&egoB, g_egoB);

    k_init<<<(NTOT * 16 + 255) / 256, 256>>>((const float4*)ue, (const float4*)ie);

    // CSR build
    k_hist<<<(NNZ + 255) / 256, 256>>>(rows);
    k_scanA<<<NBLK_SCAN, 1024>>>();
    k_scanB<<<1, 256>>>();
    k_scanC<<<NBLK_SCAN, 1024>>>();
    k_fill<<<(NNZ + 255) / 256, 256>>>(rows, cols, vals);

    // 3 fused layers, ping-pong fp16 ego buffers; last layer writes no ego
    __half2* ins[3]  = {egoA, egoB, egoA};
    __half2* outs[3] = {egoB, egoA, nullptr};
    for (int l = 0; l < 3; l++)
        k_layer<<<(NTOT + 31) / 32, 256>>>(ins[l], outs[l], Wl[l], Bl[l]);

    k_out<<<(BATCH * 16 + 255) / 256, 256>>>(users, (float4*)d_out);
}

// round 6
// speedup vs baseline: 1.2898x; 1.1296x over previous
#include <cuda_runtime.h>
#include <cuda_fp16.h>
#include <cstdint>

#define N_USER 50000
#define N_ITEM 100000
#define NTOT   150000
#define NNZ    3000000
#define EMB    64
#define BATCH  4096
#define NBLK_SCAN 147   // ceil(150000/1024)
#define ECAP   2944     // smem edge-slab capacity (mean 640, ~90 sigma headroom)

// ---------------- device scratch (no allocation allowed) --------------------
__device__ __align__(16) __half2 g_egoA[(size_t)NTOT * 32];   // fp16 ego ping
__device__ __align__(16) __half2 g_egoB[(size_t)NTOT * 32];   // fp16 ego pong
__device__ __align__(16) float   g_total[(size_t)NTOT * EMB]; // fp32 accumulator
__device__ __align__(16) unsigned long long g_edges[NNZ + 8]; // {col lo32, val hi32}
__device__ int g_cnt[NTOT];
__device__ int g_start[NTOT + 1];   // +1: sentinel = NNZ
__device__ int g_cur[NTOT];
__device__ int g_bsum[NBLK_SCAN];

// ---------------------------------------------------------------------------
// init: total = concat(user_emb, item_emb) (fp32); egoA = fp16(same); cnt = 0
// ---------------------------------------------------------------------------
__global__ void k_init(const float4* __restrict__ ue, const float4* __restrict__ ie) {
    int i = blockIdx.x * blockDim.x + threadIdx.x;   // NTOT*16 float4s
    if (i < NTOT) g_cnt[i] = 0;
    if (i >= NTOT * 16) return;
    float4 v = (i < N_USER * 16) ? ue[i] : ie[i - N_USER * 16];
    reinterpret_cast<float4*>(g_total)[i] = v;
    g_egoA[2 * i]     = __floats2half2_rn(v.x, v.y);
    g_egoA[2 * i + 1] = __floats2half2_rn(v.z, v.w);
}

// ---------------------------------------------------------------------------
// CSR build
// ---------------------------------------------------------------------------
__global__ void k_hist(const int* __restrict__ rows) {
    int i = blockIdx.x * blockDim.x + threadIdx.x;
    if (i < NNZ) atomicAdd(&g_cnt[rows[i]], 1);
}

__global__ void k_scanA() {
    __shared__ int s[1024];
    int t = threadIdx.x;
    int g = blockIdx.x * 1024 + t;
    int v = (g < NTOT) ? g_cnt[g] : 0;
    s[t] = v;
    __syncthreads();
#pragma unroll
    for (int off = 1; off < 1024; off <<= 1) {
        int add = (t >= off) ? s[t - off] : 0;
        __syncthreads();
        s[t] += add;
        __syncthreads();
    }
    if (g < NTOT) g_start[g] = s[t] - v;
    if (t == 1023) g_bsum[blockIdx.x] = s[1023];
}

__global__ void k_scanB() {
    __shared__ int s[256];
    int t = threadIdx.x;
    int v = (t < NBLK_SCAN) ? g_bsum[t] : 0;
    s[t] = v;
    __syncthreads();
#pragma unroll
    for (int off = 1; off < 256; off <<= 1) {
        int add = (t >= off) ? s[t - off] : 0;
        __syncthreads();
        s[t] += add;
        __syncthreads();
    }
    if (t < NBLK_SCAN) g_bsum[t] = s[t] - v;
}

__global__ void k_scanC() {
    int g = blockIdx.x * 1024 + threadIdx.x;
    if (g == 0) g_start[NTOT] = NNZ;           // sentinel
    if (g >= NTOT) return;
    int off = g_start[g] + g_bsum[blockIdx.x];
    g_start[g] = off;
    g_cur[g]   = off;
}

__global__ void k_fill(const int* __restrict__ rows, const int* __restrict__ cols,
                       const float* __restrict__ vals) {
    int i = blockIdx.x * blockDim.x + threadIdx.x;
    if (i >= NNZ) return;
    int r = rows[i];
    int p = atomicAdd(&g_cur[r], 1);
    g_edges[p] = (unsigned long long)(unsigned)cols[i]
               | ((unsigned long long)__float_as_uint(vals[i]) << 32);
}

// ---------------------------------------------------------------------------
// fused layer. Block = 32 consecutive rows (8 warps x 4 rows).
// The block's CSR edge slab [start(32B), start(32B+32)) is staged in smem by a
// coalesced cooperative load, so the per-chunk chain becomes
// LDS(29cyc) -> gather(L2) instead of LDG(L2) -> gather(L2). Per row the
// gather runs an 8-wide branch-free unrolled loop (last chunk clamp+zero).
// Fallback: if the slab exceeds ECAP (practically impossible), the whole
// block reads edges from global (block-uniform branch).
// ---------------------------------------------------------------------------
__global__ void __launch_bounds__(256)
k_layer(const __half2* __restrict__ ego_in, __half2* __restrict__ ego_out,
        const float* __restrict__ W, const float* __restrict__ b) {
    __shared__ float Ws[EMB * EMB];
    __shared__ float srow[8][EMB][4];   // [warp][k][row-in-group]
    __shared__ uint2 sE[ECAP];

    int tid = threadIdx.x;
    int blkRow0  = blockIdx.x * 32;
    int blkStart = g_start[min(blkRow0, NTOT)];
    int blkEnd   = g_start[min(blkRow0 + 32, NTOT)];
    int count    = blkEnd - blkStart;
    bool inSmem  = (count <= ECAP);

    for (int i = tid; i < EMB * EMB / 4; i += 256)
        reinterpret_cast<float4*>(Ws)[i] = reinterpret_cast<const float4*>(W)[i];
    if (inSmem) {
        const uint2* ge = reinterpret_cast<const uint2*>(&g_edges[blkStart]);
        for (int i = tid; i < count; i += 256)
            sE[i] = ge[i];
    }
    __syncthreads();

    int warp = tid >> 5, lane = tid & 31;
    int r0 = blkRow0 + warp * 4;

    // per-row degree + local offset
    int nn[4], lo[4];
#pragma unroll
    for (int r = 0; r < 4; r++) {
        int row = r0 + r;
        if (row < NTOT) {
            int s = g_start[row];
            nn[r] = g_start[row + 1] - s;
            lo[r] = s - blkStart;
        } else { nn[r] = 0; lo[r] = 0; }
    }

    // ---- phase 1: gather (8-wide, branch-free last chunk) ----
    float2 acc[4];
    if (inSmem) {
#pragma unroll
        for (int r = 0; r < 4; r++) {
            int n = nn[r], base0 = lo[r];
            float2 a = make_float2(0.f, 0.f);
            for (int base = 0; base < n; base += 8) {
#pragma unroll
                for (int t = 0; t < 8; t++) {
                    int idx = base + t;
                    int ic  = idx < n ? idx : n - 1;     // clamp (n>=1 here)
                    uint2 e = sE[base0 + ic];
                    __half2 x = ego_in[(size_t)e.x * 32 + lane];
                    float v = idx < n ? __uint_as_float(e.y) : 0.f;
                    float2 f = __half22float2(x);
                    a.x += v * f.x;
                    a.y += v * f.y;
                }
            }
            acc[r] = a;
        }
    } else {   // overflow fallback: read edges straight from global
        const uint2* ge = reinterpret_cast<const uint2*>(g_edges);
#pragma unroll
        for (int r = 0; r < 4; r++) {
            int n = nn[r], base0 = blkStart + lo[r];
            float2 a = make_float2(0.f, 0.f);
            for (int base = 0; base < n; base += 8) {
#pragma unroll
                for (int t = 0; t < 8; t++) {
                    int idx = base + t;
                    int ic  = idx < n ? idx : n - 1;
                    uint2 e = __ldcs(&ge[base0 + ic]);
                    __half2 x = ego_in[(size_t)e.x * 32 + lane];
                    float v = idx < n ? __uint_as_float(e.y) : 0.f;
                    float2 f = __half22float2(x);
                    a.x += v * f.x;
                    a.y += v * f.y;
                }
            }
            acc[r] = a;
        }
    }

#pragma unroll
    for (int r = 0; r < 4; r++) {
        srow[warp][2 * lane][r]     = acc[r].x;
        srow[warp][2 * lane + 1][r] = acc[r].y;
    }
    __syncwarp();

    // ---- phase 2: batched 4-row matmul (W in smem) ----
    const float2 bias = *reinterpret_cast<const float2*>(&b[2 * lane]);
    float2 o0 = bias, o1 = bias, o2 = bias, o3 = bias;
#pragma unroll
    for (int k = 0; k < EMB; k++) {
        float4 s4 = *reinterpret_cast<const float4*>(&srow[warp][k][0]);  // bcast
        float2 wk = *reinterpret_cast<const float2*>(&Ws[k * EMB + 2 * lane]);
        o0.x += s4.x * wk.x; o0.y += s4.x * wk.y;
        o1.x += s4.y * wk.x; o1.y += s4.y * wk.y;
        o2.x += s4.z * wk.x; o2.y += s4.z * wk.y;
        o3.x += s4.w * wk.x; o3.y += s4.w * wk.y;
    }

    // ---- phase 3: leaky_relu, fp16 ego_out (skipped last layer), l2norm ----
    float2 os[4] = {o0, o1, o2, o3};
#pragma unroll
    for (int r = 0; r < 4; r++) {
        int row = r0 + r;
        if (row >= NTOT) break;
        float2 e;
        e.x = os[r].x > 0.f ? os[r].x : 0.2f * os[r].x;
        e.y = os[r].y > 0.f ? os[r].y : 0.2f * os[r].y;

        if (ego_out) ego_out[(size_t)row * 32 + lane] = __floats2half2_rn(e.x, e.y);

        float ss = e.x * e.x + e.y * e.y;
#pragma unroll
        for (int off = 16; off; off >>= 1)
            ss += __shfl_xor_sync(0xffffffffu, ss, off);
        float inv = 1.f / fmaxf(sqrtf(ss), 1e-12f);

        float2* tp = reinterpret_cast<float2*>(&g_total[(size_t)row * EMB + 2 * lane]);
        float2 t = *tp;
        t.x += e.x * inv;
        t.y += e.y * inv;
        *tp = t;
    }
}

// ---------------------------------------------------------------------------
__global__ void k_out(const int* __restrict__ users, float4* __restrict__ out) {
    int i = blockIdx.x * blockDim.x + threadIdx.x;  // BATCH*16 float4s
    if (i >= BATCH * 16) return;
    int bidx = i >> 4, q = i & 15;
    int u = users[bidx];
    out[i] = reinterpret_cast<const float4*>(g_total)[(size_t)u * 16 + q];
}

// ---------------------------------------------------------------------------
extern "C" void kernel_launch(void* const* d_in, const int* in_sizes, int n_in,
                              void* d_out, int out_size) {
    const int*   users = (const int*)d_in[0];
    const int*   rows  = (const int*)d_in[1];
    const int*   cols  = (const int*)d_in[2];
    const float* vals  = (const float*)d_in[3];
    const float* ue    = (const float*)d_in[4];
    const float* ie    = (const float*)d_in[5];
    const float* Wl[3] = {(const float*)d_in[6], (const float*)d_in[8],  (const float*)d_in[10]};
    const float* Bl[3] = {(const float*)d_in[7], (const float*)d_in[9],  (const float*)d_in[11]};

    __half2 *egoA, *egoB;
    cudaGetSymbolAddress((void**)&egoA, g_egoA);
    cudaGetSymbolAddress((void**)&egoB, g_egoB);

    k_init<<<(NTOT * 16 + 255) / 256, 256>>>((const float4*)ue, (const float4*)ie);

    // CSR build
    k_hist<<<(NNZ + 255) / 256, 256>>>(rows);
    k_scanA<<<NBLK_SCAN, 1024>>>();
    k_scanB<<<1, 256>>>();
    k_scanC<<<NBLK_SCAN, 1024>>>();
    k_fill<<<(NNZ + 255) / 256, 256>>>(rows, cols, vals);

    // 3 fused layers, ping-pong fp16 ego buffers; last layer writes no ego
    __half2* ins[3]  = {egoA, egoB, egoA};
    __half2* outs[3] = {egoB, egoA, nullptr};
    for (int l = 0; l < 3; l++)
        k_layer<<<(NTOT + 31) / 32, 256>>>(ins[l], outs[l], Wl[l], Bl[l]);

    k_out<<<(BATCH * 16 + 255) / 256, 256>>>(users, (float4*)d_out);
}

// round 7
// speedup vs baseline: 1.3060x; 1.0126x over previous
#include <cuda_runtime.h>
#include <cuda_fp16.h>
#include <cstdint>

#define N_USER 50000
#define N_ITEM 100000
#define NTOT   150000
#define NNZ    3000000
#define EMB    64
#define BATCH  4096

// ---------------- device scratch (no allocation allowed) --------------------
__device__ __align__(16) __half2 g_egoA[(size_t)NTOT * 32];   // fp16 ego ping
__device__ __align__(16) __half2 g_egoB[(size_t)NTOT * 32];   // fp16 ego pong
__device__ __align__(16) float   g_total[(size_t)NTOT * EMB]; // fp32 accumulator
__device__ __align__(16) unsigned long long g_edges[NNZ + 8]; // {col lo32, val hi32}
__device__ int g_cnt[NTOT];
__device__ int g_start[NTOT];
__device__ int g_cur[NTOT];
__device__ int g_ctr;

// ---------------------------------------------------------------------------
// init: total = concat(user_emb, item_emb) (fp32); egoA = fp16(same); cnt = 0
// ---------------------------------------------------------------------------
__global__ void k_init(const float4* __restrict__ ue, const float4* __restrict__ ie) {
    int i = blockIdx.x * blockDim.x + threadIdx.x;   // NTOT*16 float4s
    if (i == 0) g_ctr = 0;
    if (i < NTOT) g_cnt[i] = 0;
    if (i >= NTOT * 16) return;
    float4 v = (i < N_USER * 16) ? ue[i] : ie[i - N_USER * 16];
    reinterpret_cast<float4*>(g_total)[i] = v;
    g_egoA[2 * i]     = __floats2half2_rn(v.x, v.y);
    g_egoA[2 * i + 1] = __floats2half2_rn(v.z, v.w);
}

// ---------------------------------------------------------------------------
// CSR build: histogram -> atomic segment allocation -> permute
// (segment placement order is atomic-nondeterministic; so is within-row edge
//  order — exactly as before with k_fill. Values stay within tolerance.)
// ---------------------------------------------------------------------------
__global__ void k_hist(const int* __restrict__ rows) {
    int i = blockIdx.x * blockDim.x + threadIdx.x;
    if (i < NNZ) atomicAdd(&g_cnt[rows[i]], 1);
}

__global__ void k_alloc() {
    int r = blockIdx.x * blockDim.x + threadIdx.x;
    if (r >= NTOT) return;
    int s = atomicAdd(&g_ctr, g_cnt[r]);
    g_start[r] = s;
    g_cur[r]   = s;
}

__global__ void k_fill(const int* __restrict__ rows, const int* __restrict__ cols,
                       const float* __restrict__ vals) {
    int i = blockIdx.x * blockDim.x + threadIdx.x;
    if (i >= NNZ) return;
    int r = rows[i];
    int p = atomicAdd(&g_cur[r], 1);
    g_edges[p] = (unsigned long long)(unsigned)cols[i]
               | ((unsigned long long)__float_as_uint(vals[i]) << 32);
}

// ---------------------------------------------------------------------------
// fused layer.  Warp = 4 rows (serial per row); lane owns cols {2l, 2l+1}.
// Per row: 8-wide unrolled gather with an in-loop predicated tail
// (idx clamped to n-1, val zeroed) — no branches, no serial tail loop,
// 8 edge loads + 8 gathers in flight per chunk.
// ---------------------------------------------------------------------------
__global__ void __launch_bounds__(256)
k_layer(const __half2* __restrict__ ego_in, __half2* __restrict__ ego_out,
        const float* __restrict__ W, const float* __restrict__ b) {
    __shared__ float Ws[EMB * EMB];
    __shared__ float srow[8][EMB][4];   // [warp][k][row-in-group]

    int tid = threadIdx.x;
    for (int i = tid; i < EMB * EMB / 4; i += 256)
        reinterpret_cast<float4*>(Ws)[i] = reinterpret_cast<const float4*>(W)[i];
    __syncthreads();

    int warp = tid >> 5, lane = tid & 31;
    int r0 = (blockIdx.x * 8 + warp) * 4;
    if (r0 >= NTOT) return;

    const uint2* ge = reinterpret_cast<const uint2*>(g_edges);

    // ---- phase 1: segmented gather, 4 rows serial, 8-wide each ----
#pragma unroll
    for (int r = 0; r < 4; r++) {
        int row = r0 + r;
        float2 acc = make_float2(0.f, 0.f);
        int n = 0, s = 0;
        if (row < NTOT) { n = g_cnt[row]; s = g_start[row]; }
        const uint2* ep = &ge[s];

        for (int base = 0; base < n; base += 8) {
            uint2 e[8];
#pragma unroll
            for (int t = 0; t < 8; t++) {
                int idx = base + t;
                int ic  = idx < n ? idx : n - 1;   // clamp (n>=1 inside loop)
                e[t] = ep[ic];
            }
#pragma unroll
            for (int t = 0; t < 8; t++) {
                __half2 x = ego_in[(size_t)e[t].x * 32 + lane];
                float v = (base + t < n) ? __uint_as_float(e[t].y) : 0.f;
                float2 f = __half22float2(x);
                acc.x += v * f.x;
                acc.y += v * f.y;
            }
        }
        srow[warp][2 * lane][r]     = acc.x;
        srow[warp][2 * lane + 1][r] = acc.y;
    }
    __syncwarp();

    // ---- phase 2: batched 4-row matmul (W in smem) ----
    const float2 bias = *reinterpret_cast<const float2*>(&b[2 * lane]);
    float2 o0 = bias, o1 = bias, o2 = bias, o3 = bias;
#pragma unroll
    for (int k = 0; k < EMB; k++) {
        float4 s4 = *reinterpret_cast<const float4*>(&srow[warp][k][0]);  // bcast
        float2 wk = *reinterpret_cast<const float2*>(&Ws[k * EMB + 2 * lane]);
        o0.x += s4.x * wk.x; o0.y += s4.x * wk.y;
        o1.x += s4.y * wk.x; o1.y += s4.y * wk.y;
        o2.x += s4.z * wk.x; o2.y += s4.z * wk.y;
        o3.x += s4.w * wk.x; o3.y += s4.w * wk.y;
    }

    // ---- phase 3: leaky_relu, fp16 ego_out (skipped last layer), l2norm ----
    float2 os[4] = {o0, o1, o2, o3};
#pragma unroll
    for (int r = 0; r < 4; r++) {
        int row = r0 + r;
        if (row >= NTOT) break;
        float2 e;
        e.x = os[r].x > 0.f ? os[r].x : 0.2f * os[r].x;
        e.y = os[r].y > 0.f ? os[r].y : 0.2f * os[r].y;

        if (ego_out) ego_out[(size_t)row * 32 + lane] = __floats2half2_rn(e.x, e.y);

        float ss = e.x * e.x + e.y * e.y;
#pragma unroll
        for (int off = 16; off; off >>= 1)
            ss += __shfl_xor_sync(0xffffffffu, ss, off);
        float inv = 1.f / fmaxf(sqrtf(ss), 1e-12f);

        float2* tp = reinterpret_cast<float2*>(&g_total[(size_t)row * EMB + 2 * lane]);
        float2 t = *tp;
        t.x += e.x * inv;
        t.y += e.y * inv;
        *tp = t;
    }
}

// ---------------------------------------------------------------------------
__global__ void k_out(const int* __restrict__ users, float4* __restrict__ out) {
    int i = blockIdx.x * blockDim.x + threadIdx.x;  // BATCH*16 float4s
    if (i >= BATCH * 16) return;
    int bidx = i >> 4, q = i & 15;
    int u = users[bidx];
    out[i] = reinterpret_cast<const float4*>(g_total)[(size_t)u * 16 + q];
}

// ---------------------------------------------------------------------------
extern "C" void kernel_launch(void* const* d_in, const int* in_sizes, int n_in,
                              void* d_out, int out_size) {
    const int*   users = (const int*)d_in[0];
    const int*   rows  = (const int*)d_in[1];
    const int*   cols  = (const int*)d_in[2];
    const float* vals  = (const float*)d_in[3];
    const float* ue    = (const float*)d_in[4];
    const float* ie    = (const float*)d_in[5];
    const float* Wl[3] = {(const float*)d_in[6], (const float*)d_in[8],  (const float*)d_in[10]};
    const float* Bl[3] = {(const float*)d_in[7], (const float*)d_in[9],  (const float*)d_in[11]};

    __half2 *egoA, *egoB;
    cudaGetSymbolAddress((void**)&egoA, g_egoA);
    cudaGetSymbolAddress((void**)&egoB, g_egoB);

    k_init<<<(NTOT * 16 + 255) / 256, 256>>>((const float4*)ue, (const float4*)ie);

    // CSR build (3 kernels)
    k_hist<<<(NNZ + 255) / 256, 256>>>(rows);
    k_alloc<<<(NTOT + 255) / 256, 256>>>();
    k_fill<<<(NNZ + 255) / 256, 256>>>(rows, cols, vals);

    // 3 fused layers, ping-pong fp16 ego buffers; last layer writes no ego
    __half2* ins[3]  = {egoA, egoB, egoA};
    __half2* outs[3] = {egoB, egoA, nullptr};
    for (int l = 0; l < 3; l++)
        k_layer<<<(NTOT + 31) / 32, 256>>>(ins[l], outs[l], Wl[l], Bl[l]);

    k_out<<<(BATCH * 16 + 255) / 256, 256>>>(users, (float4*)d_out);
}

// round 8
// speedup vs baseline: 1.4868x; 1.1385x over previous
#include <cuda_runtime.h>
#include <cuda_fp16.h>
#include <cstdint>

#define N_USER 50000
#define N_ITEM 100000
#define NTOT   150000
#define NNZ    3000000
#define EMB    64
#define BATCH  4096
#define NBLK_SCAN 147   // ceil(150000/1024)

// ---------------- device scratch (no allocation allowed) --------------------
__device__ __align__(16) __half2 g_egoA[(size_t)NTOT * 32];   // fp16 ego ping
__device__ __align__(16) __half2 g_egoB[(size_t)NTOT * 32];   // fp16 ego pong
__device__ __align__(16) float   g_total[(size_t)NTOT * EMB]; // fp32 accumulator
__device__ __align__(16) unsigned long long g_edges[NNZ + 8]; // {col lo32, val hi32}
__device__ int g_cnt[NTOT];
__device__ int g_start[NTOT];
__device__ int g_cur[NTOT];
__device__ int g_bsum[NBLK_SCAN];

// ---------------------------------------------------------------------------
// init: total = concat(user_emb, item_emb) (fp32); egoA = fp16(same); cnt = 0
// ---------------------------------------------------------------------------
__global__ void k_init(const float4* __restrict__ ue, const float4* __restrict__ ie) {
    int i = blockIdx.x * blockDim.x + threadIdx.x;   // NTOT*16 float4s
    if (i < NTOT) g_cnt[i] = 0;
    if (i >= NTOT * 16) return;
    float4 v = (i < N_USER * 16) ? ue[i] : ie[i - N_USER * 16];
    reinterpret_cast<float4*>(g_total)[i] = v;
    g_egoA[2 * i]     = __floats2half2_rn(v.x, v.y);
    g_egoA[2 * i + 1] = __floats2half2_rn(v.z, v.w);
}

// ---------------------------------------------------------------------------
// CSR build (scan-based, as in the 420us best)
// ---------------------------------------------------------------------------
__global__ void k_hist(const int* __restrict__ rows) {
    int i = blockIdx.x * blockDim.x + threadIdx.x;
    if (i < NNZ) atomicAdd(&g_cnt[rows[i]], 1);
}

__global__ void k_scanA() {
    __shared__ int s[1024];
    int t = threadIdx.x;
    int g = blockIdx.x * 1024 + t;
    int v = (g < NTOT) ? g_cnt[g] : 0;
    s[t] = v;
    __syncthreads();
#pragma unroll
    for (int off = 1; off < 1024; off <<= 1) {
        int add = (t >= off) ? s[t - off] : 0;
        __syncthreads();
        s[t] += add;
        __syncthreads();
    }
    if (g < NTOT) g_start[g] = s[t] - v;
    if (t == 1023) g_bsum[blockIdx.x] = s[1023];
}

__global__ void k_scanB() {
    __shared__ int s[256];
    int t = threadIdx.x;
    int v = (t < NBLK_SCAN) ? g_bsum[t] : 0;
    s[t] = v;
    __syncthreads();
#pragma unroll
    for (int off = 1; off < 256; off <<= 1) {
        int add = (t >= off) ? s[t - off] : 0;
        __syncthreads();
        s[t] += add;
        __syncthreads();
    }
    if (t < NBLK_SCAN) g_bsum[t] = s[t] - v;
}

__global__ void k_scanC() {
    int g = blockIdx.x * 1024 + threadIdx.x;
    if (g >= NTOT) return;
    int off = g_start[g] + g_bsum[blockIdx.x];
    g_start[g] = off;
    g_cur[g]   = off;
}

__global__ void k_fill(const int* __restrict__ rows, const int* __restrict__ cols,
                       const float* __restrict__ vals) {
    int i = blockIdx.x * blockDim.x + threadIdx.x;
    if (i >= NNZ) return;
    int r = rows[i];
    int p = atomicAdd(&g_cur[r], 1);
    g_edges[p] = (unsigned long long)(unsigned)cols[i]
               | ((unsigned long long)__float_as_uint(vals[i]) << 32);
}

// ---------------------------------------------------------------------------
// fused layer. Warp = 4 rows (serial); lane owns cols {2l, 2l+1}.
// Gather loop is 4-wide with ONE-CHUNK-AHEAD edge prefetch: gathers consume
// the previous iteration's edge regs while the next 4 edge loads are already
// in flight -> edge latency leaves the dependency chain. Tail is folded into
// the loop via clamped indices + zeroed vals (no serial tail, no divergence).
// launch_bounds(256,6) caps regs at ~42 so occupancy stays >= 48 warps/SM.
// ---------------------------------------------------------------------------
__global__ void __launch_bounds__(256, 6)
k_layer(const __half2* __restrict__ ego_in, __half2* __restrict__ ego_out,
        const float* __restrict__ W, const float* __restrict__ b) {
    __shared__ float Ws[EMB * EMB];
    __shared__ float srow[8][EMB][4];   // [warp][k][row-in-group]

    int tid = threadIdx.x;
    for (int i = tid; i < EMB * EMB / 4; i += 256)
        reinterpret_cast<float4*>(Ws)[i] = reinterpret_cast<const float4*>(W)[i];
    __syncthreads();

    int warp = tid >> 5, lane = tid & 31;
    int r0 = (blockIdx.x * 8 + warp) * 4;
    if (r0 >= NTOT) return;

    const uint2* ge = reinterpret_cast<const uint2*>(g_edges);

    // ---- phase 1: segmented gather, 4 rows serial, prefetched 4-wide ----
#pragma unroll
    for (int r = 0; r < 4; r++) {
        int row = r0 + r;
        float2 acc = make_float2(0.f, 0.f);
        int n = 0, s = 0;
        if (row < NTOT) { n = g_cnt[row]; s = g_start[row]; }
        const uint2* ep = &ge[s];

        if (n > 0) {                       // warp-uniform
            int nc = n - 1;
            // preload chunk 0 (clamped)
            uint2 e0 = ep[0];
            uint2 e1 = ep[min(1, nc)];
            uint2 e2 = ep[min(2, nc)];
            uint2 e3 = ep[min(3, nc)];
            for (int base = 0; base < n; base += 4) {
                uint2 c0 = e0, c1 = e1, c2 = e2, c3 = e3;
                // prefetch next chunk (clamped; always in-bounds)
                int nb = base + 4;
                e0 = ep[min(nb,     nc)];
                e1 = ep[min(nb + 1, nc)];
                e2 = ep[min(nb + 2, nc)];
                e3 = ep[min(nb + 3, nc)];
                // gathers on current chunk
                __half2 x0 = ego_in[(size_t)c0.x * 32 + lane];
                __half2 x1 = ego_in[(size_t)c1.x * 32 + lane];
                __half2 x2 = ego_in[(size_t)c2.x * 32 + lane];
                __half2 x3 = ego_in[(size_t)c3.x * 32 + lane];
                float v0 = __uint_as_float(c0.y);                       // always valid
                float v1 = (base + 1 < n) ? __uint_as_float(c1.y) : 0.f;
                float v2 = (base + 2 < n) ? __uint_as_float(c2.y) : 0.f;
                float v3 = (base + 3 < n) ? __uint_as_float(c3.y) : 0.f;
                float2 f0 = __half22float2(x0);
                float2 f1 = __half22float2(x1);
                float2 f2 = __half22float2(x2);
                float2 f3 = __half22float2(x3);
                acc.x += v0 * f0.x; acc.y += v0 * f0.y;
                acc.x += v1 * f1.x; acc.y += v1 * f1.y;
                acc.x += v2 * f2.x; acc.y += v2 * f2.y;
                acc.x += v3 * f3.x; acc.y += v3 * f3.y;
            }
        }
        srow[warp][2 * lane][r]     = acc.x;
        srow[warp][2 * lane + 1][r] = acc.y;
    }
    __syncwarp();

    // ---- phase 2: batched 4-row matmul (W in smem) ----
    const float2 bias = *reinterpret_cast<const float2*>(&b[2 * lane]);
    float2 o0 = bias, o1 = bias, o2 = bias, o3 = bias;
#pragma unroll
    for (int k = 0; k < EMB; k++) {
        float4 s4 = *reinterpret_cast<const float4*>(&srow[warp][k][0]);  // bcast
        float2 wk = *reinterpret_cast<const float2*>(&Ws[k * EMB + 2 * lane]);
        o0.x += s4.x * wk.x; o0.y += s4.x * wk.y;
        o1.x += s4.y * wk.x; o1.y += s4.y * wk.y;
        o2.x += s4.z * wk.x; o2.y += s4.z * wk.y;
        o3.x += s4.w * wk.x; o3.y += s4.w * wk.y;
    }

    // ---- phase 3: leaky_relu, fp16 ego_out (skipped last layer), l2norm ----
    float2 os[4] = {o0, o1, o2, o3};
#pragma unroll
    for (int r = 0; r < 4; r++) {
        int row = r0 + r;
        if (row >= NTOT) break;
        float2 e;
        e.x = os[r].x > 0.f ? os[r].x : 0.2f * os[r].x;
        e.y = os[r].y > 0.f ? os[r].y : 0.2f * os[r].y;

        if (ego_out) ego_out[(size_t)row * 32 + lane] = __floats2half2_rn(e.x, e.y);

        float ss = e.x * e.x + e.y * e.y;
#pragma unroll
        for (int off = 16; off; off >>= 1)
            ss += __shfl_xor_sync(0xffffffffu, ss, off);
        float inv = 1.f / fmaxf(sqrtf(ss), 1e-12f);

        float2* tp = reinterpret_cast<float2*>(&g_total[(size_t)row * EMB + 2 * lane]);
        float2 t = *tp;
        t.x += e.x * inv;
        t.y += e.y * inv;
        *tp = t;
    }
}

// ---------------------------------------------------------------------------
__global__ void k_out(const int* __restrict__ users, float4* __restrict__ out) {
    int i = blockIdx.x * blockDim.x + threadIdx.x;  // BATCH*16 float4s
    if (i >= BATCH * 16) return;
    int bidx = i >> 4, q = i & 15;
    int u = users[bidx];
    out[i] = reinterpret_cast<const float4*>(g_total)[(size_t)u * 16 + q];
}

// ---------------------------------------------------------------------------
extern "C" void kernel_launch(void* const* d_in, const int* in_sizes, int n_in,
                              void* d_out, int out_size) {
    const int*   users = (const int*)d_in[0];
    const int*   rows  = (const int*)d_in[1];
    const int*   cols  = (const int*)d_in[2];
    const float* vals  = (const float*)d_in[3];
    const float* ue    = (const float*)d_in[4];
    const float* ie    = (const float*)d_in[5];
    const float* Wl[3] = {(const float*)d_in[6], (const float*)d_in[8],  (const float*)d_in[10]};
    const float* Bl[3] = {(const float*)d_in[7], (const float*)d_in[9],  (const float*)d_in[11]};

    __half2 *egoA, *egoB;
    cudaGetSymbolAddress((void**)&egoA, g_egoA);
    cudaGetSymbolAddress((void**)&egoB, g_egoB);

    k_init<<<(NTOT * 16 + 255) / 256, 256>>>((const float4*)ue, (const float4*)ie);

    // CSR build
    k_hist<<<(NNZ + 255) / 256, 256>>>(rows);
    k_scanA<<<NBLK_SCAN, 1024>>>();
    k_scanB<<<1, 256>>>();
    k_scanC<<<NBLK_SCAN, 1024>>>();
    k_fill<<<(NNZ + 255) / 256, 256>>>(rows, cols, vals);

    // 3 fused layers, ping-pong fp16 ego buffers; last layer writes no ego
    __half2* ins[3]  = {egoA, egoB, egoA};
    __half2* outs[3] = {egoB, egoA, nullptr};
    for (int l = 0; l < 3; l++)
        k_layer<<<(NTOT + 31) / 32, 256>>>(ins[l], outs[l], Wl[l], Bl[l]);

    k_out<<<(BATCH * 16 + 255) / 256, 256>>>(users, (float4*)d_out);
}

// round 9
// speedup vs baseline: 1.6039x; 1.0787x over previous
#include <cuda_runtime.h>
#include <cuda_fp16.h>
#include <cstdint>

#define N_USER 50000
#define N_ITEM 100000
#define NTOT   150000
#define NNZ    3000000
#define EMB    64
#define BATCH  4096

// ---------------- device scratch (no allocation allowed) --------------------
__device__ __align__(16) __half2 g_egoA[(size_t)NTOT * 32];   // init ego, then layer-3 ego
__device__ __align__(16) __half2 g_egoB[(size_t)NTOT * 32];   // layer-1 ego
__device__ __align__(16) __half2 g_egoC[(size_t)NTOT * 32];   // layer-2 ego
__device__ float g_inv[3][NTOT];                              // per-layer inv norms
__device__ __align__(16) unsigned long long g_edges[NNZ + 8]; // {col lo32, val hi32}
__device__ int g_cnt[NTOT];     // zeroed by k_out at end of every call
__device__ int g_start[NTOT];
__device__ int g_cur[NTOT];
__device__ int g_ctr;           // zeroed by k_out at end of every call

// ---------------------------------------------------------------------------
// launch 0: fused init + histogram. g_cnt/g_ctr are zero at entry
// (module-load zeros on call 1; k_out re-zeroes at the end of every call).
// ---------------------------------------------------------------------------
__global__ void k_init_hist(const float4* __restrict__ ue, const float4* __restrict__ ie,
                            const int* __restrict__ rows) {
    int i = blockIdx.x * blockDim.x + threadIdx.x;   // grid covers NNZ
    if (i < NTOT * 16) {
        float4 v = (i < N_USER * 16) ? ue[i] : ie[i - N_USER * 16];
        g_egoA[2 * i]     = __floats2half2_rn(v.x, v.y);
        g_egoA[2 * i + 1] = __floats2half2_rn(v.z, v.w);
    }
    if (i < NNZ) atomicAdd(&g_cnt[rows[i]], 1);
}

// launch 1: atomic segment allocation
__global__ void k_alloc() {
    int r = blockIdx.x * blockDim.x + threadIdx.x;
    if (r >= NTOT) return;
    int s = atomicAdd(&g_ctr, g_cnt[r]);
    g_start[r] = s;
    g_cur[r]   = s;
}

// launch 2: permute edges into row-grouped segments
__global__ void k_fill(const int* __restrict__ rows, const int* __restrict__ cols,
                       const float* __restrict__ vals) {
    int i = blockIdx.x * blockDim.x + threadIdx.x;
    if (i >= NNZ) return;
    int r = rows[i];
    int p = atomicAdd(&g_cur[r], 1);
    g_edges[p] = (unsigned long long)(unsigned)cols[i]
               | ((unsigned long long)__float_as_uint(vals[i]) << 32);
}

// ---------------------------------------------------------------------------
// launches 3-5: fused layer. Warp = 4 rows; lane owns cols {2l, 2l+1}.
// Gather: 4-wide, one-chunk-ahead edge prefetch, predicated tail.
// Epilogue: leaky_relu -> fp16 ego_out + fp32 inv-norm (no g_total RMW).
// ---------------------------------------------------------------------------
__global__ void __launch_bounds__(256, 6)
k_layer(const __half2* __restrict__ ego_in, __half2* __restrict__ ego_out,
        float* __restrict__ inv_out,
        const float* __restrict__ W, const float* __restrict__ b) {
    __shared__ float Ws[EMB * EMB];
    __shared__ float srow[8][EMB][4];   // [warp][k][row-in-group]

    int tid = threadIdx.x;
    for (int i = tid; i < EMB * EMB / 4; i += 256)
        reinterpret_cast<float4*>(Ws)[i] = reinterpret_cast<const float4*>(W)[i];
    __syncthreads();

    int warp = tid >> 5, lane = tid & 31;
    int r0 = (blockIdx.x * 8 + warp) * 4;
    if (r0 >= NTOT) return;

    const uint2* ge = reinterpret_cast<const uint2*>(g_edges);

    // ---- phase 1: segmented gather, 4 rows serial, prefetched 4-wide ----
#pragma unroll
    for (int r = 0; r < 4; r++) {
        int row = r0 + r;
        float2 acc = make_float2(0.f, 0.f);
        int n = 0, s = 0;
        if (row < NTOT) { n = g_cnt[row]; s = g_start[row]; }
        const uint2* ep = &ge[s];

        if (n > 0) {                       // warp-uniform
            int nc = n - 1;
            uint2 e0 = ep[0];
            uint2 e1 = ep[min(1, nc)];
            uint2 e2 = ep[min(2, nc)];
            uint2 e3 = ep[min(3, nc)];
            for (int base = 0; base < n; base += 4) {
                uint2 c0 = e0, c1 = e1, c2 = e2, c3 = e3;
                int nb = base + 4;
                e0 = ep[min(nb,     nc)];
                e1 = ep[min(nb + 1, nc)];
                e2 = ep[min(nb + 2, nc)];
                e3 = ep[min(nb + 3, nc)];
                __half2 x0 = ego_in[(size_t)c0.x * 32 + lane];
                __half2 x1 = ego_in[(size_t)c1.x * 32 + lane];
                __half2 x2 = ego_in[(size_t)c2.x * 32 + lane];
                __half2 x3 = ego_in[(size_t)c3.x * 32 + lane];
                float v0 = __uint_as_float(c0.y);
                float v1 = (base + 1 < n) ? __uint_as_float(c1.y) : 0.f;
                float v2 = (base + 2 < n) ? __uint_as_float(c2.y) : 0.f;
                float v3 = (base + 3 < n) ? __uint_as_float(c3.y) : 0.f;
                float2 f0 = __half22float2(x0);
                float2 f1 = __half22float2(x1);
                float2 f2 = __half22float2(x2);
                float2 f3 = __half22float2(x3);
                acc.x += v0 * f0.x; acc.y += v0 * f0.y;
                acc.x += v1 * f1.x; acc.y += v1 * f1.y;
                acc.x += v2 * f2.x; acc.y += v2 * f2.y;
                acc.x += v3 * f3.x; acc.y += v3 * f3.y;
            }
        }
        srow[warp][2 * lane][r]     = acc.x;
        srow[warp][2 * lane + 1][r] = acc.y;
    }
    __syncwarp();

    // ---- phase 2: batched 4-row matmul (W in smem) ----
    const float2 bias = *reinterpret_cast<const float2*>(&b[2 * lane]);
    float2 o0 = bias, o1 = bias, o2 = bias, o3 = bias;
#pragma unroll
    for (int k = 0; k < EMB; k++) {
        float4 s4 = *reinterpret_cast<const float4*>(&srow[warp][k][0]);  // bcast
        float2 wk = *reinterpret_cast<const float2*>(&Ws[k * EMB + 2 * lane]);
        o0.x += s4.x * wk.x; o0.y += s4.x * wk.y;
        o1.x += s4.y * wk.x; o1.y += s4.y * wk.y;
        o2.x += s4.z * wk.x; o2.y += s4.z * wk.y;
        o3.x += s4.w * wk.x; o3.y += s4.w * wk.y;
    }

    // ---- phase 3: leaky_relu -> fp16 ego_out + inv-norm ----
    float2 os[4] = {o0, o1, o2, o3};
#pragma unroll
    for (int r = 0; r < 4; r++) {
        int row = r0 + r;
        if (row >= NTOT) break;
        float2 e;
        e.x = os[r].x > 0.f ? os[r].x : 0.2f * os[r].x;
        e.y = os[r].y > 0.f ? os[r].y : 0.2f * os[r].y;

        ego_out[(size_t)row * 32 + lane] = __floats2half2_rn(e.x, e.y);

        float ss = e.x * e.x + e.y * e.y;
#pragma unroll
        for (int off = 16; off; off >>= 1)
            ss += __shfl_xor_sync(0xffffffffu, ss, off);
        if (lane == 0)
            inv_out[row] = 1.f / fmaxf(sqrtf(ss), 1e-12f);
    }
}

// ---------------------------------------------------------------------------
// launch 6: out[u] = ue[u] + sum_l ego_l[u] * inv_l[u].
// Layer egos live in: B = layer1, C = layer2, A = layer3 (A was recycled).
// Also re-zeroes g_cnt / g_ctr for the next invocation.
// ---------------------------------------------------------------------------
__global__ void k_out(const int* __restrict__ users, const float* __restrict__ ue,
                      float* __restrict__ out) {
    int i = blockIdx.x * blockDim.x + threadIdx.x;   // grid covers max(BATCH*EMB, NTOT)
    if (i < NTOT) g_cnt[i] = 0;
    if (i == 0)   g_ctr = 0;
    if (i >= BATCH * EMB) return;
    int row = i >> 6, col = i & 63;
    int u = users[row];
    const __half* e1 = reinterpret_cast<const __half*>(g_egoB);  // layer 1
    const __half* e2 = reinterpret_cast<const __half*>(g_egoC);  // layer 2
    const __half* e3 = reinterpret_cast<const __half*>(g_egoA);  // layer 3
    size_t idx = (size_t)u * EMB + col;
    out[i] = ue[idx]
           + __half2float(e1[idx]) * g_inv[0][u]
           + __half2float(e2[idx]) * g_inv[1][u]
           + __half2float(e3[idx]) * g_inv[2][u];
}

// ---------------------------------------------------------------------------
extern "C" void kernel_launch(void* const* d_in, const int* in_sizes, int n_in,
                              void* d_out, int out_size) {
    const int*   users = (const int*)d_in[0];
    const int*   rows  = (const int*)d_in[1];
    const int*   cols  = (const int*)d_in[2];
    const float* vals  = (const float*)d_in[3];
    const float* ue    = (const float*)d_in[4];
    const float* ie    = (const float*)d_in[5];
    const float* Wl[3] = {(const float*)d_in[6], (const float*)d_in[8],  (const float*)d_in[10]};
    const float* Bl[3] = {(const float*)d_in[7], (const float*)d_in[9],  (const float*)d_in[11]};

    __half2 *egoA, *egoB, *egoC;
    float* invBase;
    cudaGetSymbolAddress((void**)&egoA, g_egoA);
    cudaGetSymbolAddress((void**)&egoB, g_egoB);
    cudaGetSymbolAddress((void**)&egoC, g_egoC);
    cudaGetSymbolAddress((void**)&invBase, g_inv);

    // 0: fused init + histogram; 1: alloc; 2: fill
    k_init_hist<<<(NNZ + 255) / 256, 256>>>((const float4*)ue, (const float4*)ie, rows);
    k_alloc<<<(NTOT + 255) / 256, 256>>>();
    k_fill<<<(NNZ + 255) / 256, 256>>>(rows, cols, vals);

    // 3-5: layers (layer0 = launch #3 -> lands in the ncu capture window)
    k_layer<<<(NTOT + 31) / 32, 256>>>(egoA, egoB, invBase + 0 * NTOT, Wl[0], Bl[0]);
    k_layer<<<(NTOT + 31) / 32, 256>>>(egoB, egoC, invBase + 1 * NTOT, Wl[1], Bl[1]);
    k_layer<<<(NTOT + 31) / 32, 256>>>(egoC, egoA, invBase + 2 * NTOT, Wl[2], Bl[2]);

    // 6: output gather + counter re-zero
    k_out<<<(BATCH * EMB + 255) / 256, 256>>>(users, ue, (float*)d_out);
}

// round 10
// speedup vs baseline: 1.7093x; 1.0657x over previous
#include <cuda_runtime.h>
#include <cuda_fp16.h>
#include <cstdint>

#define N_USER 50000
#define N_ITEM 100000
#define NTOT   150000
#define NNZ    3000000
#define EMB    64
#define BATCH  4096
#define NPAD   (NNZ + NTOT * 4 + 8)   // edges + worst-case per-row padding

// ---------------- device scratch (no allocation allowed) --------------------
__device__ __align__(16) __half2 g_egoA[(size_t)NTOT * 32];   // init ego, then layer-3 ego
__device__ __align__(16) __half2 g_egoB[(size_t)NTOT * 32];   // layer-1 ego
__device__ __align__(16) __half2 g_egoC[(size_t)NTOT * 32];   // layer-2 ego
__device__ float g_inv[3][NTOT];                              // per-layer inv norms
__device__ __align__(16) unsigned g_edges[(size_t)NPAD * 2];  // {col, valbits} pairs
__device__ int g_cnt[NTOT];     // zeroed by k_out at end of every call
__device__ int g_start[NTOT];
__device__ int g_cur[NTOT];
__device__ int g_ctr;           // zeroed by k_out at end of every call

// ---------------------------------------------------------------------------
// launch 0: fused init + histogram + edge-array zero (pad slots must be 0
// before k_fill writes the real edges). g_cnt/g_ctr zero at entry.
// ---------------------------------------------------------------------------
__global__ void k_init_hist(const float4* __restrict__ ue, const float4* __restrict__ ie,
                            const int* __restrict__ rows) {
    int i = blockIdx.x * blockDim.x + threadIdx.x;   // grid covers NNZ (3M)
    if (i < NTOT * 16) {
        float4 v = (i < N_USER * 16) ? ue[i] : ie[i - N_USER * 16];
        g_egoA[2 * i]     = __floats2half2_rn(v.x, v.y);
        g_egoA[2 * i + 1] = __floats2half2_rn(v.z, v.w);
    }
    // zero the edge array (each thread covers up to 2 slots of NPAD)
    uint2* ez = reinterpret_cast<uint2*>(g_edges);
    if (i < NPAD) ez[i] = make_uint2(0u, 0u);
    if (i + NNZ < NPAD) ez[i + NNZ] = make_uint2(0u, 0u);
    if (i < NNZ) atomicAdd(&g_cnt[rows[i]], 1);
}

// launch 1: atomic segment allocation, sizes rounded up to multiple of 4
// edges (32B) so segments are uint4-aligned and the gather loop needs no
// clamps (pad slots hold val=0).
__global__ void k_alloc() {
    int r = blockIdx.x * blockDim.x + threadIdx.x;
    if (r >= NTOT) return;
    int c4 = (g_cnt[r] + 3) & ~3;
    int s = atomicAdd(&g_ctr, c4);
    g_start[r] = s;
    g_cur[r]   = s;
}

// launch 2: permute edges into row-grouped segments
__global__ void k_fill(const int* __restrict__ rows, const int* __restrict__ cols,
                       const float* __restrict__ vals) {
    int i = blockIdx.x * blockDim.x + threadIdx.x;
    if (i >= NNZ) return;
    int r = rows[i];
    int p = atomicAdd(&g_cur[r], 1);
    uint2* ez = reinterpret_cast<uint2*>(g_edges);
    ez[p] = make_uint2((unsigned)cols[i], __float_as_uint(vals[i]));
}

// ---------------------------------------------------------------------------
// launches 3-5: fused layer. Warp = 4 rows; lane owns cols {2l, 2l+1}.
// Gather loop has NO clamps / NO SELs (rows padded to multiple of 4 with
// val=0 edges) and loads 4 edges with 2 uniform LDG.128.
// ---------------------------------------------------------------------------
__global__ void __launch_bounds__(256, 6)
k_layer(const __half2* __restrict__ ego_in, __half2* __restrict__ ego_out,
        float* __restrict__ inv_out,
        const float* __restrict__ W, const float* __restrict__ b) {
    __shared__ float Ws[EMB * EMB];
    __shared__ float srow[8][EMB][4];   // [warp][k][row-in-group]

    int tid = threadIdx.x;
    for (int i = tid; i < EMB * EMB / 4; i += 256)
        reinterpret_cast<float4*>(Ws)[i] = reinterpret_cast<const float4*>(W)[i];
    __syncthreads();

    int warp = tid >> 5, lane = tid & 31;
    int r0 = (blockIdx.x * 8 + warp) * 4;
    if (r0 >= NTOT) return;

    const __half2* egoL = ego_in + lane;   // per-lane base

    // ---- phase 1: segmented gather, 4 rows serial, clamp-free 4-wide ----
#pragma unroll
    for (int r = 0; r < 4; r++) {
        int row = r0 + r;
        float2 acc = make_float2(0.f, 0.f);
        int n4 = 0, s = 0;
        if (row < NTOT) { n4 = (g_cnt[row] + 3) & ~3; s = g_start[row]; }
        const uint4* ep = reinterpret_cast<const uint4*>(&g_edges[(size_t)s * 2]);

        for (int base = 0; base < n4; base += 4) {
            uint4 A = ep[(base >> 1)];       // edges {0,1}: {col0,val0,col1,val1}
            uint4 B = ep[(base >> 1) + 1];   // edges {2,3}
            __half2 x0 = egoL[(size_t)A.x * 32];
            __half2 x1 = egoL[(size_t)A.z * 32];
            __half2 x2 = egoL[(size_t)B.x * 32];
            __half2 x3 = egoL[(size_t)B.z * 32];
            float v0 = __uint_as_float(A.y);
            float v1 = __uint_as_float(A.w);
            float v2 = __uint_as_float(B.y);
            float v3 = __uint_as_float(B.w);
            float2 f0 = __half22float2(x0);
            float2 f1 = __half22float2(x1);
            float2 f2 = __half22float2(x2);
            float2 f3 = __half22float2(x3);
            acc.x += v0 * f0.x; acc.y += v0 * f0.y;
            acc.x += v1 * f1.x; acc.y += v1 * f1.y;
            acc.x += v2 * f2.x; acc.y += v2 * f2.y;
            acc.x += v3 * f3.x; acc.y += v3 * f3.y;
        }
        srow[warp][2 * lane][r]     = acc.x;
        srow[warp][2 * lane + 1][r] = acc.y;
    }
    __syncwarp();

    // ---- phase 2: batched 4-row matmul (W in smem) ----
    const float2 bias = *reinterpret_cast<const float2*>(&b[2 * lane]);
    float2 o0 = bias, o1 = bias, o2 = bias, o3 = bias;
#pragma unroll
    for (int k = 0; k < EMB; k++) {
        float4 s4 = *reinterpret_cast<const float4*>(&srow[warp][k][0]);  // bcast
        float2 wk = *reinterpret_cast<const float2*>(&Ws[k * EMB + 2 * lane]);
        o0.x += s4.x * wk.x; o0.y += s4.x * wk.y;
        o1.x += s4.y * wk.x; o1.y += s4.y * wk.y;
        o2.x += s4.z * wk.x; o2.y += s4.z * wk.y;
        o3.x += s4.w * wk.x; o3.y += s4.w * wk.y;
    }

    // ---- phase 3: leaky_relu -> fp16 ego_out + inv-norm ----
    float2 os[4] = {o0, o1, o2, o3};
#pragma unroll
    for (int r = 0; r < 4; r++) {
        int row = r0 + r;
        if (row >= NTOT) break;
        float2 e;
        e.x = os[r].x > 0.f ? os[r].x : 0.2f * os[r].x;
        e.y = os[r].y > 0.f ? os[r].y : 0.2f * os[r].y;

        ego_out[(size_t)row * 32 + lane] = __floats2half2_rn(e.x, e.y);

        float ss = e.x * e.x + e.y * e.y;
#pragma unroll
        for (int off = 16; off; off >>= 1)
            ss += __shfl_xor_sync(0xffffffffu, ss, off);
        if (lane == 0)
            inv_out[row] = 1.f / fmaxf(sqrtf(ss), 1e-12f);
    }
}

// ---------------------------------------------------------------------------
// launch 6: out[u] = ue[u] + sum_l ego_l[u] * inv_l[u].
// Layer egos: B = layer1, C = layer2, A = layer3. Re-zeroes g_cnt / g_ctr.
// ---------------------------------------------------------------------------
__global__ void k_out(const int* __restrict__ users, const float* __restrict__ ue,
                      float* __restrict__ out) {
    int i = blockIdx.x * blockDim.x + threadIdx.x;
    if (i < NTOT) g_cnt[i] = 0;
    if (i == 0)   g_ctr = 0;
    if (i >= BATCH * EMB) return;
    int row = i >> 6, col = i & 63;
    int u = users[row];
    const __half* e1 = reinterpret_cast<const __half*>(g_egoB);
    const __half* e2 = reinterpret_cast<const __half*>(g_egoC);
    const __half* e3 = reinterpret_cast<const __half*>(g_egoA);
    size_t idx = (size_t)u * EMB + col;
    out[i] = ue[idx]
           + __half2float(e1[idx]) * g_inv[0][u]
           + __half2float(e2[idx]) * g_inv[1][u]
           + __half2float(e3[idx]) * g_inv[2][u];
}

// ---------------------------------------------------------------------------
extern "C" void kernel_launch(void* const* d_in, const int* in_sizes, int n_in,
                              void* d_out, int out_size) {
    const int*   users = (const int*)d_in[0];
    const int*   rows  = (const int*)d_in[1];
    const int*   cols  = (const int*)d_in[2];
    const float* vals  = (const float*)d_in[3];
    const float* ue    = (const float*)d_in[4];
    const float* ie    = (const float*)d_in[5];
    const float* Wl[3] = {(const float*)d_in[6], (const float*)d_in[8],  (const float*)d_in[10]};
    const float* Bl[3] = {(const float*)d_in[7], (const float*)d_in[9],  (const float*)d_in[11]};

    __half2 *egoA, *egoB, *egoC;
    float* invBase;
    cudaGetSymbolAddress((void**)&egoA, g_egoA);
    cudaGetSymbolAddress((void**)&egoB, g_egoB);
    cudaGetSymbolAddress((void**)&egoC, g_egoC);
    cudaGetSymbolAddress((void**)&invBase, g_inv);

    // 0: init + hist + edge-zero; 1: alloc (padded); 2: fill
    k_init_hist<<<(NNZ + 255) / 256, 256>>>((const float4*)ue, (const float4*)ie, rows);
    k_alloc<<<(NTOT + 255) / 256, 256>>>();
    k_fill<<<(NNZ + 255) / 256, 256>>>(rows, cols, vals);

    // 3-5: layers (layer0 = launch #3 -> ncu capture window)
    k_layer<<<(NTOT + 31) / 32, 256>>>(egoA, egoB, invBase + 0 * NTOT, Wl[0], Bl[0]);
    k_layer<<<(NTOT + 31) / 32, 256>>>(egoB, egoC, invBase + 1 * NTOT, Wl[1], Bl[1]);
    k_layer<<<(NTOT + 31) / 32, 256>>>(egoC, egoA, invBase + 2 * NTOT, Wl[2], Bl[2]);

    // 6: output gather + counter re-zero
    k_out<<<(BATCH * EMB + 255) / 256, 256>>>(users, ue, (float*)d_out);
}